// round 17
// baseline (speedup 1.0000x reference)
#include <cuda_runtime.h>

#define FULLMASK 0xffffffffu
#define IH 256
#define IW 192

typedef unsigned long long u64;

// Static zero block for image-edge halo loads (zero-initialized, never written).
// Edge lanes point their halo loads here instead of out-of-bounds memory.
__device__ __align__(16) float g_zeros[20];

// Gaussian taps for kernel_size=11, sigma=10/6, normalized. Indexed by |d|.
static __device__ __forceinline__ float wt(int k) {
    const float t[6] = {0.23955940f, 0.20009682f, 0.11660614f,
                        0.04740849f, 0.01344761f, 0.00266126f};
    return t[k];
}

static __device__ __forceinline__ u64 pk(float lo, float hi) {
    u64 r; asm("mov.b64 %0, {%1, %2};" : "=l"(r) : "f"(lo), "f"(hi)); return r;
}
static __device__ __forceinline__ void upk(u64 v, float& lo, float& hi) {
    asm("mov.b64 {%0, %1}, %2;" : "=f"(lo), "=f"(hi) : "l"(v));
}
static __device__ __forceinline__ float f2lo(u64 v) { float a, b; upk(v, a, b); return a; }
static __device__ __forceinline__ float f2hi(u64 v) { float a, b; upk(v, a, b); return b; }
static __device__ __forceinline__ u64 f2mul(u64 a, u64 b) {
    u64 d; asm("mul.rn.f32x2 %0, %1, %2;" : "=l"(d) : "l"(a), "l"(b)); return d;
}
static __device__ __forceinline__ u64 f2fma(u64 a, u64 b, u64 c) {
    u64 d; asm("fma.rn.f32x2 %0, %1, %2, %3;" : "=l"(d) : "l"(a), "l"(b), "l"(c)); return d;
}
static __device__ __forceinline__ u64 f2add(u64 a, u64 b) {
    u64 d; asm("add.rn.f32x2 %0, %1, %2;" : "=l"(d) : "l"(a), "l"(b)); return d;
}

// HBLUR-FIRST + GATHER-VBLUR step (no warp shuffles in the hot path):
//  1. Horizontal blur of raw row r (held in Ac: 7 aligned pairs + 2 edge
//     scalars = cols c0-5..c0+10, self-loaded incl. halos) -> ring[U].
//  2. EMIT: vertical gather over the 11-slot ring (symmetric pre-adds) ->
//     output row ro = r-5; fold row max into the running argmax.
//  3. Load raw row r+1 (own 6 cols + 10 halo cols; halos are L1 hits; image
//     edges read from g_zeros via pointer select) into Ac.
//  U      : static slot phase (i mod 11)
//  GUARD  : head/tail mode — runtime row bounds checks (warp-uniform)
template<int U, bool GUARD, bool EMIT>
static __device__ __forceinline__ void step(
    const float* __restrict__ rp,   // main-mode load base: row of U=0 load
    const float* __restrict__ ip,   // image base (GUARD-mode addressing)
    const float* __restrict__ zb,   // g_zeros + 6 (edge-lane halo target)
    int r, int col0,
    u64 (&Ac)[7], float& s0c, float& s15c,
    u64 (&ring)[11][3], const u64 (&w2)[6],
    bool l0, bool l31, float& bestv, int& bestlin, int ebl)
{
    // ---- 1. hblur raw row r -> ring[U] ----
    bool rowok = true;
    if (GUARD) rowok = ((unsigned)r < (unsigned)IH);
    if (rowok) {
        const float e[16] = {
            s0c,
            f2lo(Ac[0]), f2hi(Ac[0]), f2lo(Ac[1]), f2hi(Ac[1]),
            f2lo(Ac[2]), f2hi(Ac[2]), f2lo(Ac[3]), f2hi(Ac[3]),
            f2lo(Ac[4]), f2hi(Ac[4]), f2lo(Ac[5]), f2hi(Ac[5]),
            f2lo(Ac[6]), f2hi(Ac[6]),
            s15c
        };
#pragma unroll
        for (int j = 0; j < 3; ++j) {
            // symmetric pre-adds; cross-parity sums as scalar adds into fresh
            // aligned pairs (packs elided), aligned-parity sums stay packed
            const u64 t5 = pk(e[2*j + 0] + e[2*j + 10], e[2*j + 1] + e[2*j + 11]);
            const u64 t3 = pk(e[2*j + 2] + e[2*j + 8],  e[2*j + 3] + e[2*j + 9]);
            const u64 t1 = pk(e[2*j + 4] + e[2*j + 6],  e[2*j + 5] + e[2*j + 7]);
            const u64 t4 = f2add(Ac[j], Ac[j + 4]);
            const u64 t2 = f2add(Ac[j + 1], Ac[j + 3]);
            u64 s = f2mul(t5, w2[5]);
            s = f2fma(t4, w2[4], s);
            s = f2fma(t3, w2[3], s);
            s = f2fma(t2, w2[2], s);
            s = f2fma(t1, w2[1], s);
            s = f2fma(Ac[j + 2], w2[0], s);
            ring[U][j] = s;
        }
    } else {
        ring[U][0] = 0ull; ring[U][1] = 0ull; ring[U][2] = 0ull;
    }

    // ---- 2. emit output row ro = r-5 (vertical gather, symmetric) ----
    if (EMIT) {
        u64 vb[3];
#pragma unroll
        for (int j = 0; j < 3; ++j) {
            // center slot (U+6)%11; symmetric row pairs at (U+6±t)%11
            u64 s = f2mul(f2add(ring[(U + 1) % 11][j], ring[U][j]), w2[5]);
            s = f2fma(f2add(ring[(U + 2) % 11][j], ring[(U + 10) % 11][j]), w2[4], s);
            s = f2fma(f2add(ring[(U + 3) % 11][j], ring[(U + 9) % 11][j]),  w2[3], s);
            s = f2fma(f2add(ring[(U + 4) % 11][j], ring[(U + 8) % 11][j]),  w2[2], s);
            s = f2fma(f2add(ring[(U + 5) % 11][j], ring[(U + 7) % 11][j]),  w2[1], s);
            s = f2fma(ring[(U + 6) % 11][j], w2[0], s);
            vb[j] = s;
        }
        float a0, a1, a2, a3, a4, a5;
        upk(vb[0], a0, a1);
        upk(vb[1], a2, a3);
        upk(vb[2], a4, a5);
        const float m01 = fmaxf(a0, a1);
        const float m23 = fmaxf(a2, a3);
        const float m45 = fmaxf(a4, a5);
        const float rowmax = fmaxf(fmaxf(m01, m23), m45);
        if (rowmax > bestv) {        // rare
            bestv = rowmax;
            int c = 5;
            if (a4 == rowmax) c = 4;
            if (a3 == rowmax) c = 3;
            if (a2 == rowmax) c = 2;
            if (a1 == rowmax) c = 1;
            if (a0 == rowmax) c = 0;
            bestlin = ebl + U * IW + c;
        }
    }

    // ---- 3. load raw row r+1 (cols c0-5..c0+10) into Ac ----
    bool loadok = true;
    if (GUARD) loadok = ((unsigned)(r + 1) < (unsigned)IH);
    if (loadok) {
        const float* p  = GUARD ? (ip + (r + 1) * IW + col0) : (rp + U * IW);
        const float* pl = l0  ? zb : p;    // lane 0: left halo -> zeros
        const float* pr = l31 ? zb : p;    // lane 31: right halo -> zeros
        s0c   = pl[-5];
        Ac[0] = *(const u64*)(pl - 4);
        Ac[1] = *(const u64*)(pl - 2);
        Ac[2] = *(const u64*)(p);
        Ac[3] = *(const u64*)(p + 2);
        Ac[4] = *(const u64*)(p + 4);
        Ac[5] = *(const u64*)(pr + 6);
        Ac[6] = *(const u64*)(pr + 8);
        s15c  = pr[10];
    } else {
#pragma unroll
        for (int q = 0; q < 7; ++q) Ac[q] = 0ull;
        s0c = 0.f; s15c = 0.f;
    }
}

// One CTA (64 threads = 2 warps) per (b,k) image; warp w owns output rows
// [w*128, w*128+128), lane owns 6 columns + self-loaded halos. Head (11
// guarded) + main (11x11 branch-free) + tail (6 guarded).
__global__ __launch_bounds__(64, 8)
void dark_decode_kernel(const float* __restrict__ hm,
                        float* __restrict__ out, int n_img)
{
    const int img  = blockIdx.x;
    const int warp = threadIdx.x >> 5;
    const int lane = threadIdx.x & 31;
    const float* __restrict__ ip = hm + (long long)img * (IH * IW);
    const float* __restrict__ zb = g_zeros + 6;
    const int base = warp * 128;
    const int col0 = lane * 6;
    const bool l0  = (lane == 0);
    const bool l31 = (lane == 31);

    u64 w2[6];
#pragma unroll
    for (int k = 0; k < 6; ++k) w2[k] = pk(wt(k), wt(k));

    u64 ring[11][3];   // hblurred row ring; every slot written before gather

    // raw row registers: 7 aligned pairs (cols c0-4..c0+9) + 2 edge scalars
    u64 Ac[7];
    float s0c, s15c;

    // ---- prologue: load raw row base-5 (warp0: OOB -> zeros) ----
    {
        const int r0 = base - 5;
        if (r0 >= 0) {
            const float* p  = ip + r0 * IW + col0;
            const float* pl = l0  ? zb : p;
            const float* pr = l31 ? zb : p;
            s0c   = pl[-5];
            Ac[0] = *(const u64*)(pl - 4);
            Ac[1] = *(const u64*)(pl - 2);
            Ac[2] = *(const u64*)(p);
            Ac[3] = *(const u64*)(p + 2);
            Ac[4] = *(const u64*)(p + 4);
            Ac[5] = *(const u64*)(pr + 6);
            Ac[6] = *(const u64*)(pr + 8);
            s15c  = pr[10];
        } else {
#pragma unroll
            for (int q = 0; q < 7; ++q) Ac[q] = 0ull;
            s0c = 0.f; s15c = 0.f;
        }
    }

    float bestv   = -3.4e38f;
    int   bestlin = 0;

    // ---- head: i = 0..10 (r = base-5+i), guarded; emit only at i=10 ----
    {
        const int eblh = (base - 10) * IW + col0;
#define HSTEP(U, EM) step<U, true, EM>(ip, ip, zb, base - 5 + (U), col0, Ac, \
                        s0c, s15c, ring, w2, l0, l31, bestv, bestlin, eblh)
        HSTEP(0, false); HSTEP(1, false); HSTEP(2, false); HSTEP(3, false);
        HSTEP(4, false); HSTEP(5, false); HSTEP(6, false); HSTEP(7, false);
        HSTEP(8, false); HSTEP(9, false); HSTEP(10, true);
#undef HSTEP
    }

    // ---- main: i = 11..131, 11 blocks x 11 steps, branch-free ----
    // step i hblurs row base-5+i (in regs) and loads row base-4+i
    // (max load row = base+127, always in bounds).
    {
        const float* rp = ip + (base + 7) * IW + col0;   // row r+1 at ib=0,U=0
        int ebl = (base + 1) * IW + col0;                // ro at ib=0,U=0
#define MSTEP(U) step<U, false, true>(rp, ip, zb, 0, col0, Ac, s0c, s15c, \
                        ring, w2, l0, l31, bestv, bestlin, ebl)
        for (int ib = 0; ib < 11; ++ib) {
            MSTEP(0); MSTEP(1); MSTEP(2); MSTEP(3); MSTEP(4); MSTEP(5);
            MSTEP(6); MSTEP(7); MSTEP(8); MSTEP(9); MSTEP(10);
            rp  += 11 * IW;
            ebl += 11 * IW;
        }
#undef MSTEP
    }

    // ---- tail: i = 132..137 (U = 0..5, r = base+127+U), guarded, emit ----
    {
        const int eblt = (base + 122) * IW + col0;
#define TSTEP(U) step<U, true, true>(ip, ip, zb, base + 127 + (U), col0, Ac, \
                        s0c, s15c, ring, w2, l0, l31, bestv, bestlin, eblt)
        TSTEP(0); TSTEP(1); TSTEP(2); TSTEP(3); TSTEP(4); TSTEP(5);
#undef TSTEP
    }

    // intra-warp argmax reduce (larger value wins; tie -> smaller linear index)
#pragma unroll
    for (int off = 16; off >= 1; off >>= 1) {
        const float ov = __shfl_xor_sync(FULLMASK, bestv, off);
        const int   oi = __shfl_xor_sync(FULLMASK, bestlin, off);
        if (ov > bestv || (ov == bestv && oi < bestlin)) { bestv = ov; bestlin = oi; }
    }

    __shared__ float s_v[2];
    __shared__ int   s_i[2];
    if (lane == 0) { s_v[warp] = bestv; s_i[warp] = bestlin; }
    __syncthreads();
    if (warp != 0) return;

    float fv; int fl;
    {
        const float v0 = s_v[0], v1 = s_v[1];
        const int   i0 = s_i[0], i1 = s_i[1];
        if (v1 > v0 || (v1 == v0 && i1 < i0)) { fv = v1; fl = i1; }
        else                                  { fv = v0; fl = i0; }
    }
    const int py = fl / IW;
    const int px = fl - py * IW;

    float offx = 0.f, offy = 0.f;
    const bool bok = (px >= 1) && (px < IW - 1) && (py >= 1) && (py < IH - 1);
    if (bok) {
        // 39 hblur values: flat j in [0,39), rr = py-6 + j/3, cc = px-1 + j%3
        float h0 = 0.f, h1 = 0.f;
        {
            int j = lane;
            int rr = py - 6 + j / 3;
            int cc = px - 1 + (j - (j / 3) * 3);
            if (rr >= 0 && rr < IH) {
                const float* rp2 = ip + rr * IW;
                float s = 0.f;
#pragma unroll
                for (int d = -5; d <= 5; ++d) {
                    const int c = cc + d;
                    float v = 0.f;
                    if ((unsigned)c < (unsigned)IW) v = rp2[c];
                    s += v * wt(d < 0 ? -d : d);
                }
                h0 = s;
            }
            j = lane + 32;
            if (j < 39) {
                rr = py - 6 + j / 3;
                cc = px - 1 + (j - (j / 3) * 3);
                if (rr >= 0 && rr < IH) {
                    const float* rp2 = ip + rr * IW;
                    float s = 0.f;
#pragma unroll
                    for (int d = -5; d <= 5; ++d) {
                        const int c = cc + d;
                        float v = 0.f;
                        if ((unsigned)c < (unsigned)IW) v = rp2[c];
                        s += v * wt(d < 0 ? -d : d);
                    }
                    h1 = s;
                }
            }
        }
        // lanes 0..8: vertical blur -> patch entry p(a,b), a=lane/3, b=lane%3
        const int a = lane / 3;
        const int b = lane - a * 3;
        float p = 0.f;
#pragma unroll
        for (int t = 0; t < 11; ++t) {
            const int j = (a + t) * 3 + b;
            const float va = __shfl_sync(FULLMASK, h0, j & 31);
            const float vb = __shfl_sync(FULLMASK, h1, j & 31);
            const float hv = (j < 32) ? va : vb;
            p += hv * wt(t <= 5 ? 5 - t : t - 5);
        }
        const float p00 = __shfl_sync(FULLMASK, p, 0);
        const float p01 = __shfl_sync(FULLMASK, p, 1);
        const float p02 = __shfl_sync(FULLMASK, p, 2);
        const float p10 = __shfl_sync(FULLMASK, p, 3);
        const float p11 = __shfl_sync(FULLMASK, p, 4);
        const float p12 = __shfl_sync(FULLMASK, p, 5);
        const float p20 = __shfl_sync(FULLMASK, p, 6);
        const float p21 = __shfl_sync(FULLMASK, p, 7);
        const float p22 = __shfl_sync(FULLMASK, p, 8);

        const float dx  = (p12 - p10) * 0.5f;
        const float dy  = (p21 - p01) * 0.5f;
        const float dxx = p12 - 2.f * p11 + p10;
        const float dyy = p21 - 2.f * p11 + p01;
        const float dxy = (p22 - p20 - p02 + p00) * 0.25f;
        const float det = dxx * dyy - dxy * dxy;
        if (fabsf(det) >= 1e-6f && dxx < 0.f) {
            const float ox = -(dyy * dx - dxy * dy) / det;
            const float oy = -(dxx * dy - dxy * dx) / det;
            offx = fminf(fmaxf(ox, -0.5f), 0.5f);
            offy = fminf(fmaxf(oy, -0.5f), 0.5f);
        }
    }

    if (lane == 0) {
        const float xo = fminf(fmaxf((float)px + offx, 0.f), (float)(IW - 1));
        const float yo = fminf(fmaxf((float)py + offy, 0.f), (float)(IH - 1));
        out[2 * img + 0] = xo;                       // coords[...,0] = x
        out[2 * img + 1] = yo;                       // coords[...,1] = y
        out[(long long)2 * n_img + img] = fv;        // max_vals
    }
}

extern "C" void kernel_launch(void* const* d_in, const int* in_sizes, int n_in,
                              void* d_out, int out_size)
{
    const float* hm = (const float*)d_in[0];
    // d_in[1] is kernel_size (always 11 in this problem; taps are baked in)
    const int n_img = in_sizes[0] / (IH * IW);
    dark_decode_kernel<<<n_img, 64>>>(hm, (float*)d_out, n_img);
}